// round 8
// baseline (speedup 1.0000x reference)
#include <cuda_runtime.h>
#include <cuda_fp16.h>
#include <cstdint>

#define NB    16
#define NPOS  4096
#define CIN   512
#define DIMD  256
#define NTOT  (NB*NPOS)
#define NSPLIT 8

#define BK 32
#define LDAH 40    // K-major smem row: 32 halves + 8 pad (80B, 16B-multiple)
#define LDBH 136   // MN-major 128-wide row (272B)
#define LDB2H 264  // MN-major 256-wide row (528B)

#define STG_KM 30720   // A 128*40*2 (10240) + B 256*40*2 (20480)
#define STG_GD 25600   // A 32*136*2 (8704)  + B 32*264*2 (16896)

// ---------------- scratch ----------------
__device__ __half g_xh[(size_t)NTOT*CIN];
__device__ __half g_qh[(size_t)NTOT*DIMD];
__device__ __half g_kh[(size_t)NTOT*DIMD];
__device__ __half g_vh[(size_t)NTOT*DIMD];
__device__ float g_kmax[NB*DIMD];
__device__ float g_krs [NB*DIMD];
__device__ float g_vmax[NB*DIMD];
__device__ float g_vrs [NB*DIMD];
__device__ float g_gdp[(size_t)NSPLIT*NB*DIMD*DIMD];
__device__ float g_gd [(size_t)NB*DIMD*DIMD];
__device__ __half g_Wth [(size_t)3*DIMD*CIN];  // [which][d=256][k=512]
__device__ __half g_Wrth[(size_t)CIN*DIMD];    // [c=512][d=256]
__device__ __half g_Mth [(size_t)NB*CIN*DIMD]; // [b][c=512][v=256]

// ---------------- helpers ----------------
__device__ __forceinline__ float exp_fast(float x) {
    float t = x * 1.4426950408889634f;
    t = fminf(fmaxf(t, -120.f), 120.f);
    float fi = rintf(t);
    float f  = t - fi;
    float p = 1.3333558146e-3f;
    p = fmaf(p, f, 9.6181291076e-3f);
    p = fmaf(p, f, 5.5504108665e-2f);
    p = fmaf(p, f, 2.4022650696e-1f);
    p = fmaf(p, f, 6.9314718056e-1f);
    p = fmaf(p, f, 1.0f);
    return __int_as_float(((int)fi + 127) << 23) * p;
}
__device__ __forceinline__ uint32_t smem_u32(const void* p) {
    uint32_t a;
    asm("{ .reg .u64 t; cvta.to.shared.u64 t, %1; cvt.u32.u64 %0, t; }" : "=r"(a) : "l"(p));
    return a;
}
__device__ __forceinline__ uint32_t f22h(float a, float b) {
    __half2 h = __floats2half2_rn(a, b);
    return *reinterpret_cast<uint32_t*>(&h);
}
#define CP16(sa, g) asm volatile("cp.async.cg.shared.global [%0], [%1], 16;" :: "r"(sa), "l"(g))
#define CPCOMMIT()  asm volatile("cp.async.commit_group;" ::: "memory")
#define CPWAIT0()   asm volatile("cp.async.wait_group 0;" ::: "memory")
__device__ __forceinline__ void ldsm4(uint32_t (&r)[4], uint32_t addr) {
    asm volatile("ldmatrix.sync.aligned.m8n8.x4.shared.b16 {%0,%1,%2,%3}, [%4];"
        : "=r"(r[0]), "=r"(r[1]), "=r"(r[2]), "=r"(r[3]) : "r"(addr));
}
__device__ __forceinline__ void ldsm4t(uint32_t (&r)[4], uint32_t addr) {
    asm volatile("ldmatrix.sync.aligned.m8n8.x4.trans.shared.b16 {%0,%1,%2,%3}, [%4];"
        : "=r"(r[0]), "=r"(r[1]), "=r"(r[2]), "=r"(r[3]) : "r"(addr));
}
__device__ __forceinline__ void mma16816(float* d, const uint32_t* a, const uint32_t* b) {
    asm volatile(
        "mma.sync.aligned.m16n8k16.row.col.f32.f16.f16.f32 "
        "{%0,%1,%2,%3},{%4,%5,%6,%7},{%8,%9},{%0,%1,%2,%3};"
        : "+f"(d[0]), "+f"(d[1]), "+f"(d[2]), "+f"(d[3])
        : "r"(a[0]), "r"(a[1]), "r"(a[2]), "r"(a[3]), "r"(b[0]), "r"(b[1]));
}
__device__ __forceinline__ void h8_sm(uint4& u, const float* smax, const float* srin, int base) {
    __half2* h = (__half2*)&u;
#pragma unroll
    for (int j = 0; j < 4; j++) {
        float2 f = __half22float2(h[j]);
        f.x = exp_fast(f.x - smax[base + 2*j])     * srin[base + 2*j];
        f.y = exp_fast(f.y - smax[base + 2*j + 1]) * srin[base + 2*j + 1];
        h[j] = __floats2half2_rn(f.x, f.y);
    }
}

// ---------------- cp.async tile loaders (512 threads) ----------------
// K-major A 128x32 f16: 1 x 16B per thread
__device__ __forceinline__ void cpA(uint32_t sb, const __half* __restrict__ g, int ld) {
    int m = threadIdx.x >> 2, kq = (threadIdx.x & 3) << 3;
    CP16(sb + (m*LDAH + kq)*2, g + (size_t)m*ld + kq);
}
// K-major B 256x32 f16: 2 x 16B per thread
__device__ __forceinline__ void cpB(uint32_t sb, const __half* __restrict__ g, int ld) {
#pragma unroll
    for (int j = 0; j < 2; j++) {
        int idx = threadIdx.x + j*512, n = idx >> 2, kq = (idx & 3) << 3;
        CP16(sb + (n*LDAH + kq)*2, g + (size_t)n*ld + kq);
    }
}
// MN-major B 32x256 f16: 2 x 16B per thread
__device__ __forceinline__ void cpT2(uint32_t sb, const __half* __restrict__ g, int ld) {
#pragma unroll
    for (int j = 0; j < 2; j++) {
        int idx = threadIdx.x + j*512, k = idx >> 5, nq = (idx & 31) << 3;
        CP16(sb + (k*LDB2H + nq)*2, g + (size_t)k*ld + nq);
    }
}
// softmax'd A, K-major 128x32 from f16 (reg prefetch + exp + STS)
__device__ __forceinline__ uint4 pfA(const __half* __restrict__ g, int ld) {
    int m = threadIdx.x >> 2, kq = (threadIdx.x & 3) << 3;
    return *(const uint4*)(g + (size_t)m*ld + kq);
}
__device__ __forceinline__ void stA_sm(__half* As, uint4 r, const float* smax, const float* srin) {
    int m = threadIdx.x >> 2, kq = (threadIdx.x & 3) << 3;
    h8_sm(r, smax, srin, kq);
    *(uint4*)(As + m*LDAH + kq) = r;
}
// softmax'd A, MN-major 32x128 from f16
__device__ __forceinline__ uint4 pfT1(const __half* __restrict__ g, int ld) {
    int k = threadIdx.x >> 4, nq = (threadIdx.x & 15) << 3;
    return *(const uint4*)(g + (size_t)k*ld + nq);
}
__device__ __forceinline__ void stT1_sm(__half* Ts, uint4 r, const float* smax, const float* srin) {
    int k = threadIdx.x >> 4, nq = (threadIdx.x & 15) << 3;
    h8_sm(r, smax, srin, nq);
    *(uint4*)(Ts + k*LDBH + nq) = r;
}

// ---------------- compute: 16 warps 2x8, warp tile 64x32 ----------------
__device__ __forceinline__ void compute_km(uint32_t Ab, uint32_t Bb, float (&acc)[4][4][4]) {
    const int lane = threadIdx.x & 31, warp = threadIdx.x >> 5;
    const int wm = (warp >> 3) * 64, wn = (warp & 7) * 32;
#pragma unroll
    for (int kk = 0; kk < 2; kk++) {
        int k0 = kk * 16;
        uint32_t a[4][4], b[4][2];
#pragma unroll
        for (int im = 0; im < 4; im++) {
            int m0 = wm + im * 16;
            ldsm4(a[im], Ab + (((m0 + ((lane>>3)&1)*8 + (lane&7)) * LDAH + k0 + (lane>>4)*8) << 1));
        }
#pragma unroll
        for (int p = 0; p < 2; p++) {
            int n0 = wn + p * 16;
            uint32_t r[4];
            ldsm4(r, Bb + (((n0 + ((lane>>4)&1)*8 + (lane&7)) * LDAH + k0 + ((lane>>3)&1)*8) << 1));
            b[2*p][0]=r[0]; b[2*p][1]=r[1]; b[2*p+1][0]=r[2]; b[2*p+1][1]=r[3];
        }
#pragma unroll
        for (int im = 0; im < 4; im++)
#pragma unroll
            for (int in = 0; in < 4; in++)
                mma16816(acc[im][in], a[im], b[in]);
    }
}
__device__ __forceinline__ void compute_T(uint32_t Ab, uint32_t Bb, float (&acc)[4][4][4]) {
    const int lane = threadIdx.x & 31, warp = threadIdx.x >> 5;
    const int wm = (warp >> 3) * 64, wn = (warp & 7) * 32;
#pragma unroll
    for (int kk = 0; kk < 2; kk++) {
        int k0 = kk * 16;
        uint32_t a[4][4], b[4][2];
#pragma unroll
        for (int im = 0; im < 4; im++) {
            int m0 = wm + im * 16;
            ldsm4t(a[im], Ab + (((k0 + ((lane>>4)&1)*8 + (lane&7)) * LDBH + m0 + ((lane>>3)&1)*8) << 1));
        }
#pragma unroll
        for (int p = 0; p < 2; p++) {
            int n0 = wn + p * 16;
            uint32_t r[4];
            ldsm4t(r, Bb + (((k0 + ((lane>>3)&1)*8 + (lane&7)) * LDB2H + n0 + ((lane>>4)&1)*8) << 1));
            b[2*p][0]=r[0]; b[2*p][1]=r[1]; b[2*p+1][0]=r[2]; b[2*p+1][1]=r[3];
        }
#pragma unroll
        for (int im = 0; im < 4; im++)
#pragma unroll
            for (int in = 0; in < 4; in++)
                mma16816(acc[im][in], a[im], b[in]);
    }
}
__device__ __forceinline__ void zacc(float (&acc)[4][4][4]) {
#pragma unroll
    for (int i = 0; i < 4; i++)
#pragma unroll
        for (int j = 0; j < 4; j++)
#pragma unroll
            for (int r = 0; r < 4; r++) acc[i][j][r] = 0.f;
}
__device__ __forceinline__ void epi_f(float* C, int ldc, float (&acc)[4][4][4],
                                      const float* bias) {
    const int lane = threadIdx.x & 31, warp = threadIdx.x >> 5;
    const int wm = (warp >> 3) * 64, wn = (warp & 7) * 32;
    const int g = lane >> 2, t = lane & 3;
#pragma unroll
    for (int im = 0; im < 4; im++)
#pragma unroll
        for (int in = 0; in < 4; in++) {
            int row = wm + im * 16 + g, col = wn + in * 8 + t * 2;
            float b0 = 0.f, b1 = 0.f;
            if (bias) { b0 = bias[col]; b1 = bias[col + 1]; }
            *(float2*)(C + (size_t)row * ldc + col) =
                make_float2(acc[im][in][0] + b0, acc[im][in][1] + b1);
            *(float2*)(C + (size_t)(row + 8) * ldc + col) =
                make_float2(acc[im][in][2] + b0, acc[im][in][3] + b1);
        }
}
__device__ __forceinline__ void epi_h(__half* C, int ldc, float (&acc)[4][4][4],
                                      const float* bias) {
    const int lane = threadIdx.x & 31, warp = threadIdx.x >> 5;
    const int wm = (warp >> 3) * 64, wn = (warp & 7) * 32;
    const int g = lane >> 2, t = lane & 3;
#pragma unroll
    for (int im = 0; im < 4; im++)
#pragma unroll
        for (int in = 0; in < 4; in++) {
            int row = wm + im * 16 + g, col = wn + in * 8 + t * 2;
            float b0 = bias ? bias[col] : 0.f, b1 = bias ? bias[col + 1] : 0.f;
            *(__half2*)(C + (size_t)row * ldc + col) =
                __floats2half2_rn(acc[im][in][0] + b0, acc[im][in][1] + b1);
            *(__half2*)(C + (size_t)(row + 8) * ldc + col) =
                __floats2half2_rn(acc[im][in][2] + b0, acc[im][in][3] + b1);
        }
}

// ---------------- K0: x -> fp16 ----------------
__global__ void k_cvtx(const float* __restrict__ x) {
    size_t n8 = (size_t)NTOT * CIN / 8;
    for (size_t i = (size_t)blockIdx.x * blockDim.x + threadIdx.x; i < n8;
         i += (size_t)gridDim.x * blockDim.x) {
        const float4* s = (const float4*)(x + i * 8);
        float4 u = s[0], v = s[1];
        uint4 w = make_uint4(f22h(u.x,u.y), f22h(u.z,u.w), f22h(v.x,v.y), f22h(v.z,v.w));
        *(uint4*)(g_xh + i * 8) = w;
    }
}

// ---------------- weight transposes ----------------
__global__ void k_trw3(const float* __restrict__ Wq, const float* __restrict__ Wk,
                       const float* __restrict__ Wv) {
    __shared__ float t[32][33];
    const float* src = (blockIdx.z == 0) ? Wq : (blockIdx.z == 1) ? Wk : Wv;
    __half* dst = g_Wth + (size_t)blockIdx.z * DIMD * CIN;
    int bx = blockIdx.x * 32, by = blockIdx.y * 32;   // bx over DIMD, by over CIN
    for (int j = threadIdx.y; j < 32; j += 8)
        t[j][threadIdx.x] = src[(size_t)(by + j) * DIMD + bx + threadIdx.x];
    __syncthreads();
    for (int j = threadIdx.y; j < 32; j += 8)
        dst[(size_t)(bx + j) * CIN + by + threadIdx.x] = __float2half_rn(t[threadIdx.x][j]);
}
__global__ void k_trh(const float* __restrict__ src, __half* __restrict__ dst, int R, int C) {
    __shared__ float t[32][33];
    int bx = blockIdx.x * 32, by = blockIdx.y * 32;
    for (int j = threadIdx.y; j < 32; j += 8)
        t[j][threadIdx.x] = src[(size_t)(by + j) * C + bx + threadIdx.x];
    __syncthreads();
    for (int j = threadIdx.y; j < 32; j += 8)
        dst[(size_t)(bx + j) * R + by + threadIdx.x] = __float2half_rn(t[threadIdx.x][j]);
}

// ---------------- K1: QKV projection (cp.async double-buffered) ----------------
__global__ __launch_bounds__(512, 1)
void k_proj(const float* __restrict__ bq, const float* __restrict__ bk,
            const float* __restrict__ bv) {
    extern __shared__ __align__(16) char smem[];
    __shared__ float sbias[256];
    int mt = blockIdx.x, which = blockIdx.y;
    const float* bias = (which == 0) ? bq : (which == 1) ? bk : bv;
    __half* out       = (which == 0) ? g_qh : (which == 1) ? g_kh : g_vh;
    if (threadIdx.x < 256) sbias[threadIdx.x] = bias[threadIdx.x];
    const __half* A = g_xh + (size_t)mt * 128 * CIN;
    const __half* B = g_Wth + (size_t)which * DIMD * CIN;
    uint32_t s0 = smem_u32(smem);

    float acc[4][4][4];
    zacc(acc);
    cpA(s0, A, CIN); cpB(s0 + 10240, B, CIN); CPCOMMIT(); CPWAIT0();
    __syncthreads();
    const int T = CIN / BK;
    for (int i = 0; i < T; i++) {
        uint32_t cur = s0 + (i & 1) * STG_KM;
        if (i + 1 < T) {
            uint32_t nxt = s0 + ((i + 1) & 1) * STG_KM;
            cpA(nxt, A + (i + 1) * BK, CIN);
            cpB(nxt + 10240, B + (i + 1) * BK, CIN);
            CPCOMMIT();
        }
        compute_km(cur, cur + 10240, acc);
        if (i + 1 < T) CPWAIT0();
        __syncthreads();
    }
    epi_h(out + (size_t)mt * 128 * DIMD, DIMD, acc, sbias);
}

// ---------------- K2: softmax stats ----------------
__global__ void k_stats() {
    int bid = blockIdx.x;
    int b = bid >> 4, rem = bid & 15;
    int tensor = rem >> 3, cg = rem & 7;
    const __half* src = tensor ? g_vh : g_kh;
    float* omax = tensor ? g_vmax : g_kmax;
    float* orsm = tensor ? g_vrs : g_krs;
    int tx = threadIdx.x, ty = threadIdx.y;
    int ch = cg * 32 + tx;
    const __half* p = src + (size_t)b * NPOS * DIMD + ch;
    float m = -1e30f, s = 0.f;
    for (int n = ty; n < NPOS; n += 8) {
        float xv = __half2float(p[(size_t)n * DIMD]);
        if (xv > m) { s = s * exp_fast(m - xv) + 1.f; m = xv; }
        else        { s += exp_fast(xv - m); }
    }
    __shared__ float shm[8][32], shs[8][32];
    shm[ty][tx] = m; shs[ty][tx] = s;
    __syncthreads();
    if (ty == 0) {
        float M = shm[0][tx], S = shs[0][tx];
#pragma unroll
        for (int j = 1; j < 8; j++) {
            float mj = shm[j][tx], sj = shs[j][tx];
            float Mn = fmaxf(M, mj);
            S = S * exp_fast(M - Mn) + sj * exp_fast(mj - Mn);
            M = Mn;
        }
        omax[b * DIMD + ch] = M;
        orsm[b * DIMD + ch] = 1.f / S;
    }
}

// ---------------- K3: gd partials ----------------
__global__ __launch_bounds__(512, 1)
void k_gd() {
    extern __shared__ __align__(16) char smem[];
    __shared__ float smax[128], srin[128];
    int bid = blockIdx.x;
    int mt = bid & 1, sp = (bid >> 1) & 7, b = bid >> 4;
    int v0 = mt * 128;
    if (threadIdx.x < 128) {
        smax[threadIdx.x] = g_kmax[b * DIMD + v0 + threadIdx.x];
        srin[threadIdx.x] = g_krs [b * DIMD + v0 + threadIdx.x];
    }
    __syncthreads();
    const __half* Ka = g_kh + (size_t)b * NPOS * DIMD + v0;
    const __half* Qa = g_qh + (size_t)b * NPOS * DIMD;
    const size_t nbase = (size_t)sp * (NPOS / NSPLIT);
    uint32_t s0 = smem_u32(smem);

    float acc[4][4][4];
    zacc(acc);
    uint4 ra = pfT1(Ka + nbase * DIMD, DIMD);
    cpT2(s0 + 8704, Qa + nbase * DIMD, DIMD); CPCOMMIT();
    stT1_sm((__half*)smem, ra, smax, srin);
    CPWAIT0();
    __syncthreads();
    const int T = (NPOS / NSPLIT) / BK;
    for (int i = 0; i < T; i++) {
        uint32_t cur = s0 + (i & 1) * STG_GD;
        if (i + 1 < T) {
            uint32_t nxt = s0 + ((i + 1) & 1) * STG_GD;
            ra = pfT1(Ka + (nbase + (i + 1) * BK) * DIMD, DIMD);
            cpT2(nxt + 8704, Qa + (nbase + (i + 1) * BK) * DIMD, DIMD);
            CPCOMMIT();
        }
        compute_T(cur, cur + 8704, acc);
        if (i + 1 < T) {
            stT1_sm((__half*)(smem + ((i + 1) & 1) * STG_GD), ra, smax, srin);
            CPWAIT0();
        }
        __syncthreads();
    }
    epi_f(g_gdp + (((size_t)sp * NB + b) * DIMD + v0) * DIMD, DIMD, acc, nullptr);
}
__global__ void k_gdreduce() {
    size_t i = (size_t)blockIdx.x * blockDim.x + threadIdx.x;
    float s = 0.f;
#pragma unroll
    for (int sp = 0; sp < NSPLIT; sp++)
        s += g_gdp[(size_t)sp * NB * DIMD * DIMD + i];
    g_gd[i] = s;
}

// ---------------- K4: Mth = Wrt @ gd^T ----------------
__global__ __launch_bounds__(512, 1)
void k_m() {
    extern __shared__ __align__(16) char smem[];
    int mt = blockIdx.x, b = blockIdx.y;
    const __half* Asrc = g_Wrth + (size_t)mt * 128 * DIMD;
    const float*  Bsrc = g_gd + (size_t)b * DIMD * DIMD;
    __half* As = (__half*)smem;
    __half* Bs = (__half*)(smem + 10240);
    float acc[4][4][4];
    zacc(acc);
    for (int k0 = 0; k0 < DIMD; k0 += BK) {
        {
            int m = threadIdx.x >> 2, kq = (threadIdx.x & 3) << 3;
            *(uint4*)(As + m*LDAH + kq) = *(const uint4*)(Asrc + (size_t)m*DIMD + k0 + kq);
        }
#pragma unroll
        for (int j = 0; j < 4; j++) {
            int idx = threadIdx.x + j*512, n = idx >> 3, kq = (idx & 7) << 2;
            float4 u = *(const float4*)(Bsrc + (size_t)n*DIMD + k0 + kq);
            *(uint2*)(Bs + n*LDAH + kq) = make_uint2(f22h(u.x, u.y), f22h(u.z, u.w));
        }
        __syncthreads();
        compute_km(smem_u32(As), smem_u32(Bs), acc);
        __syncthreads();
    }
    epi_h(g_Mth + ((size_t)b * CIN + mt * 128) * DIMD, DIMD, acc, nullptr);
}

// ---------------- K5: out = sm(v) @ Mth^T + br ----------------
__global__ __launch_bounds__(512, 1)
void k_out(const float* __restrict__ br, float* __restrict__ out) {
    extern __shared__ __align__(16) char smem[];
    __shared__ float smax[DIMD], srin[DIMD];
    int mt = blockIdx.x, nt = blockIdx.y;
    int b = mt >> 5;
    if (threadIdx.x < DIMD) {
        smax[threadIdx.x] = g_vmax[b * DIMD + threadIdx.x];
        srin[threadIdx.x] = g_vrs [b * DIMD + threadIdx.x];
    }
    __syncthreads();
    const __half* Asrc = g_vh + (size_t)mt * 128 * DIMD;
    const __half* Bsrc = g_Mth + ((size_t)b * CIN + nt * 256) * DIMD;
    uint32_t s0 = smem_u32(smem);

    float acc[4][4][4];
    zacc(acc);
    uint4 ra = pfA(Asrc, DIMD);
    cpB(s0 + 10240, Bsrc, DIMD); CPCOMMIT();
    stA_sm((__half*)smem, ra, smax, srin);
    CPWAIT0();
    __syncthreads();
    const int T = DIMD / BK;
    for (int i = 0; i < T; i++) {
        uint32_t cur = s0 + (i & 1) * STG_KM;
        if (i + 1 < T) {
            uint32_t nxt = s0 + ((i + 1) & 1) * STG_KM;
            ra = pfA(Asrc + (i + 1) * BK, DIMD);
            cpB(nxt + 10240, Bsrc + (i + 1) * BK, DIMD);
            CPCOMMIT();
        }
        compute_km(cur, cur + 10240, acc);
        if (i + 1 < T) {
            stA_sm((__half*)(smem + ((i + 1) & 1) * STG_KM), ra,
                   smax + (i + 1) * BK, srin + (i + 1) * BK);
            CPWAIT0();
        }
        __syncthreads();
    }
    epi_f(out + (size_t)mt * 128 * CIN + nt * 256, CIN, acc, br + nt * 256);
}

// ---------------- launch ----------------
extern "C" void kernel_launch(void* const* d_in, const int* in_sizes, int n_in,
                              void* d_out, int out_size) {
    (void)in_sizes; (void)n_in; (void)out_size;
    const float* x  = (const float*)d_in[0];
    const float* Wq = (const float*)d_in[1];
    const float* bq = (const float*)d_in[2];
    const float* Wk = (const float*)d_in[3];
    const float* bk = (const float*)d_in[4];
    const float* Wv = (const float*)d_in[5];
    const float* bv = (const float*)d_in[6];
    const float* Wr = (const float*)d_in[7];
    const float* br = (const float*)d_in[8];
    float* out = (float*)d_out;

    static int smem_set = 0;
    if (!smem_set) {
        cudaFuncSetAttribute(k_proj, cudaFuncAttributeMaxDynamicSharedMemorySize, 2 * STG_KM);
        cudaFuncSetAttribute(k_gd,   cudaFuncAttributeMaxDynamicSharedMemorySize, 2 * STG_GD);
        cudaFuncSetAttribute(k_m,    cudaFuncAttributeMaxDynamicSharedMemorySize, STG_KM);
        cudaFuncSetAttribute(k_out,  cudaFuncAttributeMaxDynamicSharedMemorySize, 2 * STG_KM);
        smem_set = 1;
    }

    __half* wrt = nullptr;
    cudaGetSymbolAddress((void**)&wrt, g_Wrth);

    k_cvtx<<<2048, 256>>>(x);                                   // #1
    k_trw3<<<dim3(8, 16, 3), dim3(32, 8)>>>(Wq, Wk, Wv);        // #2
    k_trh<<<dim3(16, 8), dim3(32, 8)>>>(Wr, wrt, DIMD, CIN);    // #3
    k_proj<<<dim3(NTOT / 128, 3), 512, 2 * STG_KM>>>(bq, bk, bv); // #4 (ncu capture slot)
    k_stats<<<NB * 8 * 2, dim3(32, 8)>>>();
    k_gd<<<NB * NSPLIT * 2, 512, 2 * STG_GD>>>();
    k_gdreduce<<<(NB * DIMD * DIMD) / 256, 256>>>();
    k_m<<<dim3(4, NB), 512, STG_KM>>>();
    k_out<<<dim3(NTOT / 128, 2), 512, 2 * STG_KM>>>(br, out);
}

// round 10
// speedup vs baseline: 1.0763x; 1.0763x over previous
#include <cuda_runtime.h>
#include <cuda_fp16.h>
#include <cstdint>

#define NB    16
#define NPOS  4096
#define CIN   512
#define DIMD  256
#define NTOT  (NB*NPOS)
#define NSPLIT 8

#define BK 32
#define LDAH 40    // K-major smem row: 32 halves + 8 pad (80B)
#define LDBH 136   // MN-major 128-wide row (272B)

#define STG_KM 20480   // A 128*40*2 + B 128*40*2
#define STG_GD 17408   // A 32*136*2 + B 32*136*2

// ---------------- scratch ----------------
__device__ __half g_xh[(size_t)NTOT*CIN];
__device__ __half g_qh[(size_t)NTOT*DIMD];
__device__ __half g_kh[(size_t)NTOT*DIMD];   // after k_smapply: softmax(k)
__device__ __half g_vh[(size_t)NTOT*DIMD];   // after k_smapply: softmax(v)
__device__ float g_kmax[NB*DIMD];
__device__ float g_krs [NB*DIMD];
__device__ float g_vmax[NB*DIMD];
__device__ float g_vrs [NB*DIMD];
__device__ float g_gdp[(size_t)NSPLIT*NB*DIMD*DIMD];
__device__ __half g_gdh[(size_t)NB*DIMD*DIMD];   // [b][v][d] fp16
__device__ __half g_Wth [(size_t)3*DIMD*CIN];    // [which][d][k=512]
__device__ __half g_Wrth[(size_t)CIN*DIMD];      // [c=512][d=256]
__device__ __half g_Mth [(size_t)NB*CIN*DIMD];   // [b][c][v]

// ---------------- helpers ----------------
__device__ __forceinline__ float exp_fast(float x) {
    float t = x * 1.4426950408889634f;
    t = fminf(fmaxf(t, -120.f), 120.f);
    float fi = rintf(t);
    float f  = t - fi;
    float p = 1.3333558146e-3f;
    p = fmaf(p, f, 9.6181291076e-3f);
    p = fmaf(p, f, 5.5504108665e-2f);
    p = fmaf(p, f, 2.4022650696e-1f);
    p = fmaf(p, f, 6.9314718056e-1f);
    p = fmaf(p, f, 1.0f);
    return __int_as_float(((int)fi + 127) << 23) * p;
}
__device__ __forceinline__ uint32_t smem_u32(const void* p) {
    uint32_t a;
    asm("{ .reg .u64 t; cvta.to.shared.u64 t, %1; cvt.u32.u64 %0, t; }" : "=r"(a) : "l"(p));
    return a;
}
__device__ __forceinline__ uint32_t f22h(float a, float b) {
    __half2 h = __floats2half2_rn(a, b);
    return *reinterpret_cast<uint32_t*>(&h);
}
#define CP16(sa, g) asm volatile("cp.async.cg.shared.global [%0], [%1], 16;" :: "r"(sa), "l"(g))
#define CPCOMMIT()  asm volatile("cp.async.commit_group;" ::: "memory")
#define CPWAIT0()   asm volatile("cp.async.wait_group 0;" ::: "memory")
#define CPWAIT1()   asm volatile("cp.async.wait_group 1;" ::: "memory")
__device__ __forceinline__ void ldsm4(uint32_t (&r)[4], uint32_t addr) {
    asm volatile("ldmatrix.sync.aligned.m8n8.x4.shared.b16 {%0,%1,%2,%3}, [%4];"
        : "=r"(r[0]), "=r"(r[1]), "=r"(r[2]), "=r"(r[3]) : "r"(addr));
}
__device__ __forceinline__ void ldsm4t(uint32_t (&r)[4], uint32_t addr) {
    asm volatile("ldmatrix.sync.aligned.m8n8.x4.trans.shared.b16 {%0,%1,%2,%3}, [%4];"
        : "=r"(r[0]), "=r"(r[1]), "=r"(r[2]), "=r"(r[3]) : "r"(addr));
}
__device__ __forceinline__ void mma16816(float* d, const uint32_t* a, const uint32_t* b) {
    asm volatile(
        "mma.sync.aligned.m16n8k16.row.col.f32.f16.f16.f32 "
        "{%0,%1,%2,%3},{%4,%5,%6,%7},{%8,%9},{%0,%1,%2,%3};"
        : "+f"(d[0]), "+f"(d[1]), "+f"(d[2]), "+f"(d[3])
        : "r"(a[0]), "r"(a[1]), "r"(a[2]), "r"(a[3]), "r"(b[0]), "r"(b[1]));
}
__device__ __forceinline__ void h8_sm(uint4& u, const float* smax, const float* srin, int base) {
    __half2* h = (__half2*)&u;
#pragma unroll
    for (int j = 0; j < 4; j++) {
        float2 f = __half22float2(h[j]);
        f.x = exp_fast(f.x - smax[base + 2*j])     * srin[base + 2*j];
        f.y = exp_fast(f.y - smax[base + 2*j + 1]) * srin[base + 2*j + 1];
        h[j] = __floats2half2_rn(f.x, f.y);
    }
}

// ---------------- cp.async tile loaders (256 threads) ----------------
// K-major tile 128 rows x 32 halves
__device__ __forceinline__ void cp128(uint32_t sb, const __half* __restrict__ g, int ld) {
#pragma unroll
    for (int j = 0; j < 2; j++) {
        int idx = threadIdx.x + j*256, m = idx >> 2, kq = (idx & 3) << 3;
        CP16(sb + (m*LDAH + kq)*2, g + (size_t)m*ld + kq);
    }
}
// MN-major tile 32 k-rows x 128 halves
__device__ __forceinline__ void cpT(uint32_t sb, const __half* __restrict__ g, int ld) {
#pragma unroll
    for (int j = 0; j < 2; j++) {
        int idx = threadIdx.x + j*256, k = idx >> 4, nq = (idx & 15) << 3;
        CP16(sb + (k*LDBH + nq)*2, g + (size_t)k*ld + nq);
    }
}

// ---------------- compute: 8 warps 2x4, warp tile 64x32 (validated R5) ----------------
__device__ __forceinline__ void compute_km(uint32_t Ab, uint32_t Bb, float (&acc)[4][4][4]) {
    const int lane = threadIdx.x & 31, warp = threadIdx.x >> 5;
    const int wm = (warp >> 2) * 64, wn = (warp & 3) * 32;
#pragma unroll
    for (int kk = 0; kk < 2; kk++) {
        int k0 = kk * 16;
        uint32_t a[4][4], b[4][2];
#pragma unroll
        for (int im = 0; im < 4; im++) {
            int m0 = wm + im * 16;
            ldsm4(a[im], Ab + (((m0 + ((lane>>3)&1)*8 + (lane&7)) * LDAH + k0 + (lane>>4)*8) << 1));
        }
#pragma unroll
        for (int p = 0; p < 2; p++) {
            int n0 = wn + p * 16;
            uint32_t r[4];
            ldsm4(r, Bb + (((n0 + ((lane>>4)&1)*8 + (lane&7)) * LDAH + k0 + ((lane>>3)&1)*8) << 1));
            b[2*p][0]=r[0]; b[2*p][1]=r[1]; b[2*p+1][0]=r[2]; b[2*p+1][1]=r[3];
        }
#pragma unroll
        for (int im = 0; im < 4; im++)
#pragma unroll
            for (int in = 0; in < 4; in++)
                mma16816(acc[im][in], a[im], b[in]);
    }
}
__device__ __forceinline__ void compute_T(uint32_t Ab, uint32_t Bb, float (&acc)[4][4][4]) {
    const int lane = threadIdx.x & 31, warp = threadIdx.x >> 5;
    const int wm = (warp >> 2) * 64, wn = (warp & 3) * 32;
#pragma unroll
    for (int kk = 0; kk < 2; kk++) {
        int k0 = kk * 16;
        uint32_t a[4][4], b[4][2];
#pragma unroll
        for (int im = 0; im < 4; im++) {
            int m0 = wm + im * 16;
            ldsm4t(a[im], Ab + (((k0 + ((lane>>4)&1)*8 + (lane&7)) * LDBH + m0 + ((lane>>3)&1)*8) << 1));
        }
#pragma unroll
        for (int p = 0; p < 2; p++) {
            int n0 = wn + p * 16;
            uint32_t r[4];
            ldsm4t(r, Bb + (((k0 + ((lane>>3)&1)*8 + (lane&7)) * LDBH + n0 + ((lane>>4)&1)*8) << 1));
            b[2*p][0]=r[0]; b[2*p][1]=r[1]; b[2*p+1][0]=r[2]; b[2*p+1][1]=r[3];
        }
#pragma unroll
        for (int im = 0; im < 4; im++)
#pragma unroll
            for (int in = 0; in < 4; in++)
                mma16816(acc[im][in], a[im], b[in]);
    }
}
__device__ __forceinline__ void zacc(float (&acc)[4][4][4]) {
#pragma unroll
    for (int i = 0; i < 4; i++)
#pragma unroll
        for (int j = 0; j < 4; j++)
#pragma unroll
            for (int r = 0; r < 4; r++) acc[i][j][r] = 0.f;
}
__device__ __forceinline__ void epi_f(float* C, int ldc, float (&acc)[4][4][4],
                                      const float* bias) {
    const int lane = threadIdx.x & 31, warp = threadIdx.x >> 5;
    const int wm = (warp >> 2) * 64, wn = (warp & 3) * 32;
    const int g = lane >> 2, t = lane & 3;
#pragma unroll
    for (int im = 0; im < 4; im++)
#pragma unroll
        for (int in = 0; in < 4; in++) {
            int row = wm + im * 16 + g, col = wn + in * 8 + t * 2;
            float b0 = 0.f, b1 = 0.f;
            if (bias) { b0 = bias[col]; b1 = bias[col + 1]; }
            *(float2*)(C + (size_t)row * ldc + col) =
                make_float2(acc[im][in][0] + b0, acc[im][in][1] + b1);
            *(float2*)(C + (size_t)(row + 8) * ldc + col) =
                make_float2(acc[im][in][2] + b0, acc[im][in][3] + b1);
        }
}
__device__ __forceinline__ void epi_h(__half* C, int ldc, float (&acc)[4][4][4],
                                      const float* bias) {
    const int lane = threadIdx.x & 31, warp = threadIdx.x >> 5;
    const int wm = (warp >> 2) * 64, wn = (warp & 3) * 32;
    const int g = lane >> 2, t = lane & 3;
#pragma unroll
    for (int im = 0; im < 4; im++)
#pragma unroll
        for (int in = 0; in < 4; in++) {
            int row = wm + im * 16 + g, col = wn + in * 8 + t * 2;
            float b0 = bias ? bias[col] : 0.f, b1 = bias ? bias[col + 1] : 0.f;
            *(__half2*)(C + (size_t)row * ldc + col) =
                __floats2half2_rn(acc[im][in][0] + b0, acc[im][in][1] + b1);
            *(__half2*)(C + (size_t)(row + 8) * ldc + col) =
                __floats2half2_rn(acc[im][in][2] + b0, acc[im][in][3] + b1);
        }
}

// ---------------- 3-stage pipelined GEMM body (K-major) ----------------
#define GEMM3(CPA_EXPR, CPB_EXPR, COMPUTE, STG, BOFF, T)                       \
    do {                                                                       \
        { int i = 0; uint32_t st = s0;              CPA_EXPR; CPB_EXPR; CPCOMMIT(); } \
        { int i = 1; uint32_t st = s0 + STG;        CPA_EXPR; CPB_EXPR; CPCOMMIT(); } \
        CPWAIT1(); __syncthreads();                                            \
        for (int it = 0; it < (T); it++) {                                     \
            uint32_t cur = s0 + (it % 3) * STG;                                \
            if (it + 2 < (T)) {                                                \
                int i = it + 2; uint32_t st = s0 + ((it + 2) % 3) * STG;       \
                CPA_EXPR; CPB_EXPR; CPCOMMIT();                                \
            }                                                                  \
            COMPUTE(cur, cur + BOFF, acc);                                     \
            if (it + 2 < (T)) { CPWAIT1(); } else { CPWAIT0(); }               \
            __syncthreads();                                                   \
        }                                                                      \
    } while (0)

// ---------------- K0: x -> fp16 ----------------
__global__ void k_cvtx(const float* __restrict__ x) {
    size_t n8 = (size_t)NTOT * CIN / 8;
    for (size_t i = (size_t)blockIdx.x * blockDim.x + threadIdx.x; i < n8;
         i += (size_t)gridDim.x * blockDim.x) {
        const float4* s = (const float4*)(x + i * 8);
        float4 u = s[0], v = s[1];
        *(uint4*)(g_xh + i * 8) =
            make_uint4(f22h(u.x,u.y), f22h(u.z,u.w), f22h(v.x,v.y), f22h(v.z,v.w));
    }
}

// ---------------- weight transposes ----------------
__global__ void k_trw3(const float* __restrict__ Wq, const float* __restrict__ Wk,
                       const float* __restrict__ Wv) {
    __shared__ float t[32][33];
    const float* src = (blockIdx.z == 0) ? Wq : (blockIdx.z == 1) ? Wk : Wv;
    __half* dst = g_Wth + (size_t)blockIdx.z * DIMD * CIN;
    int bx = blockIdx.x * 32, by = blockIdx.y * 32;
    for (int j = threadIdx.y; j < 32; j += 8)
        t[j][threadIdx.x] = src[(size_t)(by + j) * DIMD + bx + threadIdx.x];
    __syncthreads();
    for (int j = threadIdx.y; j < 32; j += 8)
        dst[(size_t)(bx + j) * CIN + by + threadIdx.x] = __float2half_rn(t[threadIdx.x][j]);
}
__global__ void k_trh(const float* __restrict__ src, __half* __restrict__ dst, int R, int C) {
    __shared__ float t[32][33];
    int bx = blockIdx.x * 32, by = blockIdx.y * 32;
    for (int j = threadIdx.y; j < 32; j += 8)
        t[j][threadIdx.x] = src[(size_t)(by + j) * C + bx + threadIdx.x];
    __syncthreads();
    for (int j = threadIdx.y; j < 32; j += 8)
        dst[(size_t)(bx + j) * R + by + threadIdx.x] = __float2half_rn(t[threadIdx.x][j]);
}

// ---------------- K1: QKV projection ----------------
__global__ __launch_bounds__(256, 2)
void k_proj(const float* __restrict__ bq, const float* __restrict__ bk,
            const float* __restrict__ bv) {
    extern __shared__ __align__(16) char smem[];
    int mt = blockIdx.x, which = blockIdx.y >> 1, nt = blockIdx.y & 1;
    const float* bias = ((which == 0) ? bq : (which == 1) ? bk : bv) + nt * 128;
    __half* out       = (which == 0) ? g_qh : (which == 1) ? g_kh : g_vh;
    const __half* A = g_xh + (size_t)mt * 128 * CIN;
    const __half* B = g_Wth + ((size_t)which * DIMD + nt * 128) * CIN;
    uint32_t s0 = smem_u32(smem);

    float acc[4][4][4];
    zacc(acc);
    GEMM3(cp128(st, A + i * BK, CIN), cp128(st + 10240, B + i * BK, CIN),
          compute_km, STG_KM, 10240, CIN / BK);
    epi_h(out + ((size_t)mt * 128) * DIMD + nt * 128, DIMD, acc, bias);
}

// ---------------- K2: softmax stats ----------------
__global__ void k_stats() {
    int bid = blockIdx.x;
    int b = bid >> 4, rem = bid & 15;
    int tensor = rem >> 3, cg = rem & 7;
    const __half* src = tensor ? g_vh : g_kh;
    float* omax = tensor ? g_vmax : g_kmax;
    float* orsm = tensor ? g_vrs : g_krs;
    int tx = threadIdx.x, ty = threadIdx.y;
    int ch = cg * 32 + tx;
    const __half* p = src + (size_t)b * NPOS * DIMD + ch;
    float m = -1e30f, s = 0.f;
    for (int n = ty; n < NPOS; n += 8) {
        float xv = __half2float(p[(size_t)n * DIMD]);
        if (xv > m) { s = s * exp_fast(m - xv) + 1.f; m = xv; }
        else        { s += exp_fast(xv - m); }
    }
    __shared__ float shm[8][32], shs[8][32];
    shm[ty][tx] = m; shs[ty][tx] = s;
    __syncthreads();
    if (ty == 0) {
        float M = shm[0][tx], S = shs[0][tx];
#pragma unroll
        for (int j = 1; j < 8; j++) {
            float mj = shm[j][tx], sj = shs[j][tx];
            float Mn = fmaxf(M, mj);
            S = S * exp_fast(M - Mn) + sj * exp_fast(mj - Mn);
            M = Mn;
        }
        omax[b * DIMD + ch] = M;
        orsm[b * DIMD + ch] = 1.f / S;
    }
}

// ---------------- K2b: apply softmax in place to k/v ----------------
__global__ void k_smapply() {
    __half* t = blockIdx.y ? g_vh : g_kh;
    const float* mx = blockIdx.y ? g_vmax : g_kmax;
    const float* rs = blockIdx.y ? g_vrs : g_krs;
    size_t n8 = (size_t)NTOT * DIMD / 8;
    for (size_t i = (size_t)blockIdx.x * blockDim.x + threadIdx.x; i < n8;
         i += (size_t)gridDim.x * blockDim.x) {
        size_t e = i * 8;
        int b = (int)(e >> 20);          // NPOS*DIMD = 2^20
        int ch = (int)(e & 255);
        uint4 u = *(const uint4*)(t + e);
        h8_sm(u, mx + b * DIMD, rs + b * DIMD, ch);
        *(uint4*)(t + e) = u;
    }
}

// ---------------- K3: gd partials (pure cp.async, trans) ----------------
__global__ __launch_bounds__(256, 2)
void k_gd() {
    extern __shared__ __align__(16) char smem[];
    int bid = blockIdx.x;
    int nt = bid & 1, mt = (bid >> 1) & 1, sp = (bid >> 2) & 7, b = bid >> 5;
    const __half* Ka = g_kh + (size_t)b * NPOS * DIMD + mt * 128;
    const __half* Qa = g_qh + (size_t)b * NPOS * DIMD + nt * 128;
    const size_t nbase = (size_t)sp * (NPOS / NSPLIT);
    uint32_t s0 = smem_u32(smem);

    float acc[4][4][4];
    zacc(acc);
    GEMM3(cpT(st, Ka + (nbase + i * BK) * DIMD, DIMD),
          cpT(st + 8704, Qa + (nbase + i * BK) * DIMD, DIMD),
          compute_T, STG_GD, 8704, (NPOS / NSPLIT) / BK);
    epi_f(g_gdp + (((size_t)sp * NB + b) * DIMD + mt * 128) * DIMD + nt * 128,
          DIMD, acc, nullptr);
}
__global__ void k_gdreduce() {
    size_t i = ((size_t)blockIdx.x * blockDim.x + threadIdx.x) * 2;
    float s0 = 0.f, s1 = 0.f;
#pragma unroll
    for (int sp = 0; sp < NSPLIT; sp++) {
        const float* p = g_gdp + (size_t)sp * NB * DIMD * DIMD + i;
        s0 += p[0]; s1 += p[1];
    }
    *(__half2*)(g_gdh + i) = __floats2half2_rn(s0, s1);
}

// ---------------- K4: Mth[b][c][v] = Wrt @ gdh^T ----------------
__global__ __launch_bounds__(256, 2)
void k_m() {
    extern __shared__ __align__(16) char smem[];
    int mt = blockIdx.x, nt = blockIdx.y, b = blockIdx.z;
    const __half* A = g_Wrth + (size_t)mt * 128 * DIMD;            // [c][d]
    const __half* B = g_gdh + ((size_t)b * DIMD + nt * 128) * DIMD; // [v][d]
    uint32_t s0 = smem_u32(smem);
    float acc[4][4][4];
    zacc(acc);
    GEMM3(cp128(st, A + i * BK, DIMD), cp128(st + 10240, B + i * BK, DIMD),
          compute_km, STG_KM, 10240, DIMD / BK);
    epi_h(g_Mth + ((size_t)b * CIN + mt * 128) * DIMD + nt * 128, DIMD, acc, nullptr);
}

// ---------------- K5: out = sm(v) @ Mth^T + br ----------------
__global__ __launch_bounds__(256, 2)
void k_out(const float* __restrict__ br, float* __restrict__ out) {
    extern __shared__ __align__(16) char smem[];
    int mt = blockIdx.x, nt = blockIdx.y;
    int b = mt >> 5;
    const __half* A = g_vh + (size_t)mt * 128 * DIMD;               // [n][v] (softmaxed)
    const __half* B = g_Mth + ((size_t)b * CIN + nt * 128) * DIMD;  // [c][v]
    uint32_t s0 = smem_u32(smem);
    float acc[4][4][4];
    zacc(acc);
    GEMM3(cp128(st, A + i * BK, DIMD), cp128(st + 10240, B + i * BK, DIMD),
          compute_km, STG_KM, 10240, DIMD / BK);
    epi_f(out + (size_t)mt * 128 * CIN + nt * 128, CIN, acc, br + nt * 128);
}

// ---------------- launch ----------------
extern "C" void kernel_launch(void* const* d_in, const int* in_sizes, int n_in,
                              void* d_out, int out_size) {
    (void)in_sizes; (void)n_in; (void)out_size;
    const float* x  = (const float*)d_in[0];
    const float* Wq = (const float*)d_in[1];
    const float* bq = (const float*)d_in[2];
    const float* Wk = (const float*)d_in[3];
    const float* bk = (const float*)d_in[4];
    const float* Wv = (const float*)d_in[5];
    const float* bv = (const float*)d_in[6];
    const float* Wr = (const float*)d_in[7];
    const float* br = (const float*)d_in[8];
    float* out = (float*)d_out;

    static int smem_set = 0;
    if (!smem_set) {
        cudaFuncSetAttribute(k_proj, cudaFuncAttributeMaxDynamicSharedMemorySize, 3 * STG_KM);
        cudaFuncSetAttribute(k_gd,   cudaFuncAttributeMaxDynamicSharedMemorySize, 3 * STG_GD);
        cudaFuncSetAttribute(k_m,    cudaFuncAttributeMaxDynamicSharedMemorySize, 3 * STG_KM);
        cudaFuncSetAttribute(k_out,  cudaFuncAttributeMaxDynamicSharedMemorySize, 3 * STG_KM);
        smem_set = 1;
    }

    __half* wrt = nullptr;
    cudaGetSymbolAddress((void**)&wrt, g_Wrth);

    k_cvtx<<<2048, 256>>>(x);                                     // #1
    k_trw3<<<dim3(8, 16, 3), dim3(32, 8)>>>(Wq, Wk, Wv);          // #2
    k_trh<<<dim3(16, 8), dim3(32, 8)>>>(Wr, wrt, DIMD, CIN);      // #3
    k_proj<<<dim3(NTOT / 128, 6), 256, 3 * STG_KM>>>(bq, bk, bv); // #4 (ncu slot)
    k_stats<<<NB * 8 * 2, dim3(32, 8)>>>();
    k_smapply<<<dim3(1024, 2), 256>>>();
    k_gd<<<NB * NSPLIT * 2 * 2, 256, 3 * STG_GD>>>();
    k_gdreduce<<<(NB * DIMD * DIMD) / 512, 256>>>();
    k_m<<<dim3(4, 2, NB), 256, 3 * STG_KM>>>();
    k_out<<<dim3(NTOT / 128, 4), 256, 3 * STG_KM>>>(br, out);
}

// round 11
// speedup vs baseline: 1.7507x; 1.6267x over previous
#include <cuda_runtime.h>
#include <cuda_fp16.h>
#include <cstdint>

#define NB    16
#define NPOS  4096
#define CIN   512
#define DIMD  256
#define NTOT  (NB*NPOS)
#define NSPLIT 4

#define BK 32
#define LDAH 40    // K-major smem row: 32 halves + 8 pad (80B)
#define LDBH 136   // MN-major 128-wide row (272B)

#define STG_KM 20480   // A 128*40*2 + B 128*40*2
#define STG_GD 17408   // A 32*136*2 + B 32*136*2

// ---------------- scratch ----------------
__device__ __half g_xh[(size_t)NTOT*CIN];
__device__ __half g_qh[(size_t)NTOT*DIMD];
__device__ __half g_kh[(size_t)NTOT*DIMD];   // exp(k~) fp16 (unnormalized)
__device__ __half g_vh[(size_t)NTOT*DIMD];   // exp(v~) fp16 (unnormalized)
__device__ float g_part[2*8*NB*DIMD];        // column-sum partials [tensor][seg][b*256+ch]
__device__ float g_krs [NB*DIMD];            // 1/S_k
__device__ float g_vrs [NB*DIMD];            // 4096/S_v
__device__ float g_gdp[(size_t)NSPLIT*NB*DIMD*DIMD];
__device__ __half g_gdh[(size_t)NB*DIMD*DIMD];   // normalized gd, fp16 [b][v][d]
__device__ __half g_Wth [(size_t)3*DIMD*CIN];    // [which][d][k=512]
__device__ __half g_Wrth[(size_t)CIN*DIMD];      // [c=512][d=256]
__device__ __half g_Mth [(size_t)NB*CIN*DIMD];   // [b][c][v]  (holds M*4096/S_v)

// ---------------- helpers ----------------
__device__ __forceinline__ float exp_fast(float x) {
    float t = x * 1.4426950408889634f;
    t = fminf(fmaxf(t, -120.f), 120.f);
    float fi = rintf(t);
    float f  = t - fi;
    float p = 1.3333558146e-3f;
    p = fmaf(p, f, 9.6181291076e-3f);
    p = fmaf(p, f, 5.5504108665e-2f);
    p = fmaf(p, f, 2.4022650696e-1f);
    p = fmaf(p, f, 6.9314718056e-1f);
    p = fmaf(p, f, 1.0f);
    return __int_as_float(((int)fi + 127) << 23) * p;
}
__device__ __forceinline__ uint32_t smem_u32(const void* p) {
    uint32_t a;
    asm("{ .reg .u64 t; cvta.to.shared.u64 t, %1; cvt.u32.u64 %0, t; }" : "=r"(a) : "l"(p));
    return a;
}
__device__ __forceinline__ uint32_t f22h(float a, float b) {
    __half2 h = __floats2half2_rn(a, b);
    return *reinterpret_cast<uint32_t*>(&h);
}
#define CP16(sa, g) asm volatile("cp.async.cg.shared.global [%0], [%1], 16;" :: "r"(sa), "l"(g))
#define CPCOMMIT()  asm volatile("cp.async.commit_group;" ::: "memory")
#define CPWAIT0()   asm volatile("cp.async.wait_group 0;" ::: "memory")
#define CPWAIT1()   asm volatile("cp.async.wait_group 1;" ::: "memory")
__device__ __forceinline__ void ldsm4(uint32_t (&r)[4], uint32_t addr) {
    asm volatile("ldmatrix.sync.aligned.m8n8.x4.shared.b16 {%0,%1,%2,%3}, [%4];"
        : "=r"(r[0]), "=r"(r[1]), "=r"(r[2]), "=r"(r[3]) : "r"(addr));
}
__device__ __forceinline__ void ldsm4t(uint32_t (&r)[4], uint32_t addr) {
    asm volatile("ldmatrix.sync.aligned.m8n8.x4.trans.shared.b16 {%0,%1,%2,%3}, [%4];"
        : "=r"(r[0]), "=r"(r[1]), "=r"(r[2]), "=r"(r[3]) : "r"(addr));
}
__device__ __forceinline__ void mma16816(float* d, const uint32_t* a, const uint32_t* b) {
    asm volatile(
        "mma.sync.aligned.m16n8k16.row.col.f32.f16.f16.f32 "
        "{%0,%1,%2,%3},{%4,%5,%6,%7},{%8,%9},{%0,%1,%2,%3};"
        : "+f"(d[0]), "+f"(d[1]), "+f"(d[2]), "+f"(d[3])
        : "r"(a[0]), "r"(a[1]), "r"(a[2]), "r"(a[3]), "r"(b[0]), "r"(b[1]));
}

// ---------------- cp.async tile loaders (256 threads) ----------------
__device__ __forceinline__ void cp128(uint32_t sb, const __half* __restrict__ g, int ld) {
#pragma unroll
    for (int j = 0; j < 2; j++) {
        int idx = threadIdx.x + j*256, m = idx >> 2, kq = (idx & 3) << 3;
        CP16(sb + (m*LDAH + kq)*2, g + (size_t)m*ld + kq);
    }
}
__device__ __forceinline__ void cpT(uint32_t sb, const __half* __restrict__ g, int ld) {
#pragma unroll
    for (int j = 0; j < 2; j++) {
        int idx = threadIdx.x + j*256, k = idx >> 4, nq = (idx & 15) << 3;
        CP16(sb + (k*LDBH + nq)*2, g + (size_t)k*ld + nq);
    }
}

// ---------------- compute: 8 warps 2x4, warp tile 64x32 ----------------
__device__ __forceinline__ void compute_km(uint32_t Ab, uint32_t Bb, float (&acc)[4][4][4]) {
    const int lane = threadIdx.x & 31, warp = threadIdx.x >> 5;
    const int wm = (warp >> 2) * 64, wn = (warp & 3) * 32;
#pragma unroll
    for (int kk = 0; kk < 2; kk++) {
        int k0 = kk * 16;
        uint32_t a[4][4], b[4][2];
#pragma unroll
        for (int im = 0; im < 4; im++) {
            int m0 = wm + im * 16;
            ldsm4(a[im], Ab + (((m0 + ((lane>>3)&1)*8 + (lane&7)) * LDAH + k0 + (lane>>4)*8) << 1));
        }
#pragma unroll
        for (int p = 0; p < 2; p++) {
            int n0 = wn + p * 16;
            uint32_t r[4];
            ldsm4(r, Bb + (((n0 + ((lane>>4)&1)*8 + (lane&7)) * LDAH + k0 + ((lane>>3)&1)*8) << 1));
            b[2*p][0]=r[0]; b[2*p][1]=r[1]; b[2*p+1][0]=r[2]; b[2*p+1][1]=r[3];
        }
#pragma unroll
        for (int im = 0; im < 4; im++)
#pragma unroll
            for (int in = 0; in < 4; in++)
                mma16816(acc[im][in], a[im], b[in]);
    }
}
__device__ __forceinline__ void compute_T(uint32_t Ab, uint32_t Bb, float (&acc)[4][4][4]) {
    const int lane = threadIdx.x & 31, warp = threadIdx.x >> 5;
    const int wm = (warp >> 2) * 64, wn = (warp & 3) * 32;
#pragma unroll
    for (int kk = 0; kk < 2; kk++) {
        int k0 = kk * 16;
        uint32_t a[4][4], b[4][2];
#pragma unroll
        for (int im = 0; im < 4; im++) {
            int m0 = wm + im * 16;
            ldsm4t(a[im], Ab + (((k0 + ((lane>>4)&1)*8 + (lane&7)) * LDBH + m0 + ((lane>>3)&1)*8) << 1));
        }
#pragma unroll
        for (int p = 0; p < 2; p++) {
            int n0 = wn + p * 16;
            uint32_t r[4];
            ldsm4t(r, Bb + (((k0 + ((lane>>3)&1)*8 + (lane&7)) * LDBH + n0 + ((lane>>4)&1)*8) << 1));
            b[2*p][0]=r[0]; b[2*p][1]=r[1]; b[2*p+1][0]=r[2]; b[2*p+1][1]=r[3];
        }
#pragma unroll
        for (int im = 0; im < 4; im++)
#pragma unroll
            for (int in = 0; in < 4; in++)
                mma16816(acc[im][in], a[im], b[in]);
    }
}
__device__ __forceinline__ void zacc(float (&acc)[4][4][4]) {
#pragma unroll
    for (int i = 0; i < 4; i++)
#pragma unroll
        for (int j = 0; j < 4; j++)
#pragma unroll
            for (int r = 0; r < 4; r++) acc[i][j][r] = 0.f;
}
// f32 epilogue with scale: C = acc*scale + bias
__device__ __forceinline__ void epi_f(float* C, int ldc, float (&acc)[4][4][4],
                                      const float* bias, float scale) {
    const int lane = threadIdx.x & 31, warp = threadIdx.x >> 5;
    const int wm = (warp >> 2) * 64, wn = (warp & 3) * 32;
    const int g = lane >> 2, t = lane & 3;
#pragma unroll
    for (int im = 0; im < 4; im++)
#pragma unroll
        for (int in = 0; in < 4; in++) {
            int row = wm + im * 16 + g, col = wn + in * 8 + t * 2;
            float b0 = 0.f, b1 = 0.f;
            if (bias) { b0 = bias[col]; b1 = bias[col + 1]; }
            *(float2*)(C + (size_t)row * ldc + col) =
                make_float2(acc[im][in][0]*scale + b0, acc[im][in][1]*scale + b1);
            *(float2*)(C + (size_t)(row + 8) * ldc + col) =
                make_float2(acc[im][in][2]*scale + b0, acc[im][in][3]*scale + b1);
        }
}
// f16 epilogue: optionally exp(acc+bias), optionally per-col scale array
__device__ __forceinline__ void epi_h(__half* C, int ldc, float (&acc)[4][4][4],
                                      const float* bias, int doexp, const float* colscale) {
    const int lane = threadIdx.x & 31, warp = threadIdx.x >> 5;
    const int wm = (warp >> 2) * 64, wn = (warp & 3) * 32;
    const int g = lane >> 2, t = lane & 3;
#pragma unroll
    for (int im = 0; im < 4; im++)
#pragma unroll
        for (int in = 0; in < 4; in++) {
            int row = wm + im * 16 + g, col = wn + in * 8 + t * 2;
            float b0 = bias ? bias[col] : 0.f, b1 = bias ? bias[col + 1] : 0.f;
            float v0 = acc[im][in][0] + b0, v1 = acc[im][in][1] + b1;
            float v2 = acc[im][in][2] + b0, v3 = acc[im][in][3] + b1;
            if (doexp) { v0 = exp_fast(v0); v1 = exp_fast(v1); v2 = exp_fast(v2); v3 = exp_fast(v3); }
            if (colscale) {
                float s0 = colscale[col], s1 = colscale[col + 1];
                v0 *= s0; v1 *= s1; v2 *= s0; v3 *= s1;
            }
            *(__half2*)(C + (size_t)row * ldc + col) = __floats2half2_rn(v0, v1);
            *(__half2*)(C + (size_t)(row + 8) * ldc + col) = __floats2half2_rn(v2, v3);
        }
}

// ---------------- 3-stage pipelined GEMM body ----------------
#define GEMM3(CPA_EXPR, CPB_EXPR, COMPUTE, STG, BOFF, T)                       \
    do {                                                                       \
        { int i = 0; uint32_t st = s0;              CPA_EXPR; CPB_EXPR; CPCOMMIT(); } \
        { int i = 1; uint32_t st = s0 + STG;        CPA_EXPR; CPB_EXPR; CPCOMMIT(); } \
        CPWAIT1(); __syncthreads();                                            \
        for (int it = 0; it < (T); it++) {                                     \
            uint32_t cur = s0 + (it % 3) * STG;                                \
            if (it + 2 < (T)) {                                                \
                int i = it + 2; uint32_t st = s0 + ((it + 2) % 3) * STG;       \
                CPA_EXPR; CPB_EXPR; CPCOMMIT();                                \
            }                                                                  \
            COMPUTE(cur, cur + BOFF, acc);                                     \
            if (it + 2 < (T)) { CPWAIT1(); } else { CPWAIT0(); }               \
            __syncthreads();                                                   \
        }                                                                      \
    } while (0)

// ---------------- K0: x -> fp16 ----------------
__global__ void k_cvtx(const float* __restrict__ x) {
    size_t n8 = (size_t)NTOT * CIN / 8;
    for (size_t i = (size_t)blockIdx.x * blockDim.x + threadIdx.x; i < n8;
         i += (size_t)gridDim.x * blockDim.x) {
        const float4* s = (const float4*)(x + i * 8);
        float4 u = s[0], v = s[1];
        *(uint4*)(g_xh + i * 8) =
            make_uint4(f22h(u.x,u.y), f22h(u.z,u.w), f22h(v.x,v.y), f22h(v.z,v.w));
    }
}

// ---------------- weight transposes ----------------
__global__ void k_trw3(const float* __restrict__ Wq, const float* __restrict__ Wk,
                       const float* __restrict__ Wv) {
    __shared__ float t[32][33];
    const float* src = (blockIdx.z == 0) ? Wq : (blockIdx.z == 1) ? Wk : Wv;
    __half* dst = g_Wth + (size_t)blockIdx.z * DIMD * CIN;
    int bx = blockIdx.x * 32, by = blockIdx.y * 32;
    for (int j = threadIdx.y; j < 32; j += 8)
        t[j][threadIdx.x] = src[(size_t)(by + j) * DIMD + bx + threadIdx.x];
    __syncthreads();
    for (int j = threadIdx.y; j < 32; j += 8)
        dst[(size_t)(bx + j) * CIN + by + threadIdx.x] = __float2half_rn(t[threadIdx.x][j]);
}
__global__ void k_trh(const float* __restrict__ src, __half* __restrict__ dst, int R, int C) {
    __shared__ float t[32][33];
    int bx = blockIdx.x * 32, by = blockIdx.y * 32;
    for (int j = threadIdx.y; j < 32; j += 8)
        t[j][threadIdx.x] = src[(size_t)(by + j) * C + bx + threadIdx.x];
    __syncthreads();
    for (int j = threadIdx.y; j < 32; j += 8)
        dst[(size_t)(bx + j) * R + by + threadIdx.x] = __float2half_rn(t[threadIdx.x][j]);
}

// ---------------- K1: QKV projection (x = which/nt fast dim for L2 reuse) ----------------
__global__ __launch_bounds__(256, 2)
void k_proj(const float* __restrict__ bq, const float* __restrict__ bk,
            const float* __restrict__ bv) {
    extern __shared__ __align__(16) char smem[];
    int which = blockIdx.x >> 1, nt = blockIdx.x & 1, mt = blockIdx.y;
    const float* bias = ((which == 0) ? bq : (which == 1) ? bk : bv) + nt * 128;
    __half* out       = (which == 0) ? g_qh : (which == 1) ? g_kh : g_vh;
    const __half* A = g_xh + (size_t)mt * 128 * CIN;
    const __half* B = g_Wth + ((size_t)which * DIMD + nt * 128) * CIN;
    uint32_t s0 = smem_u32(smem);

    float acc[4][4][4];
    zacc(acc);
    GEMM3(cp128(st, A + i * BK, CIN), cp128(st + 10240, B + i * BK, CIN),
          compute_km, STG_KM, 10240, CIN / BK);
    // k/v get exp() applied in-epilogue (no-max softmax numerator)
    epi_h(out + ((size_t)mt * 128) * DIMD + nt * 128, DIMD, acc, bias,
          which != 0, nullptr);
}

// ---------------- K2: column sums of exp(k)/exp(v) ----------------
__global__ void k_colsum() {
    int b = blockIdx.x >> 3, seg = blockIdx.x & 7, tensor = blockIdx.y;
    const __half* src = tensor ? g_vh : g_kh;
    int tid = threadIdx.x;
    const __half* p = src + ((size_t)b * NPOS + (size_t)seg * 512) * DIMD + tid;
    float s = 0.f;
#pragma unroll 4
    for (int n = 0; n < 512; n++)
        s += __half2float(p[(size_t)n * DIMD]);
    g_part[((size_t)tensor * 8 + seg) * (NB * DIMD) + b * DIMD + tid] = s;
}
__global__ void k_colfin() {
    int idx = blockIdx.x * 256 + threadIdx.x;       // 0..8191
    int tensor = idx >> 12, j = idx & 4095;
    float S = 0.f;
#pragma unroll
    for (int seg = 0; seg < 8; seg++)
        S += g_part[((size_t)tensor * 8 + seg) * (NB * DIMD) + j];
    if (tensor == 0) g_krs[j] = 1.0f / S;
    else             g_vrs[j] = 4096.0f / S;
}

// ---------------- K3: gd partials ----------------
__global__ __launch_bounds__(256, 2)
void k_gd() {
    extern __shared__ __align__(16) char smem[];
    int bid = blockIdx.x;
    int nt = bid & 1, mt = (bid >> 1) & 1, sp = (bid >> 2) & (NSPLIT - 1), b = bid >> 4;
    const __half* Ka = g_kh + (size_t)b * NPOS * DIMD + mt * 128;
    const __half* Qa = g_qh + (size_t)b * NPOS * DIMD + nt * 128;
    const size_t nbase = (size_t)sp * (NPOS / NSPLIT);
    uint32_t s0 = smem_u32(smem);

    float acc[4][4][4];
    zacc(acc);
    GEMM3(cpT(st, Ka + (nbase + i * BK) * DIMD, DIMD),
          cpT(st + 8704, Qa + (nbase + i * BK) * DIMD, DIMD),
          compute_T, STG_GD, 8704, (NPOS / NSPLIT) / BK);
    epi_f(g_gdp + (((size_t)sp * NB + b) * DIMD + mt * 128) * DIMD + nt * 128,
          DIMD, acc, nullptr, 1.0f);
}
// reduce partials + normalize by 1/S_k, emit fp16
__global__ void k_gdreduce() {
    size_t i = ((size_t)blockIdx.x * blockDim.x + threadIdx.x) * 2;
    float s0 = 0.f, s1 = 0.f;
#pragma unroll
    for (int sp = 0; sp < NSPLIT; sp++) {
        const float* p = g_gdp + (size_t)sp * NB * DIMD * DIMD + i;
        s0 += p[0]; s1 += p[1];
    }
    float sc = g_krs[i >> 8];     // i = ((b*256+v)*256+d) -> i>>8 = b*256+v
    *(__half2*)(g_gdh + i) = __floats2half2_rn(s0 * sc, s1 * sc);
}

// ---------------- K4: Mth[b][c][v] = (Wrt @ gdh^T) * (4096/S_v) ----------------
__global__ __launch_bounds__(256, 2)
void k_m() {
    extern __shared__ __align__(16) char smem[];
    int mt = blockIdx.x, nt = blockIdx.y, b = blockIdx.z;
    const __half* A = g_Wrth + (size_t)mt * 128 * DIMD;             // [c][d]
    const __half* B = g_gdh + ((size_t)b * DIMD + nt * 128) * DIMD; // [v][d]
    uint32_t s0 = smem_u32(smem);
    float acc[4][4][4];
    zacc(acc);
    GEMM3(cp128(st, A + i * BK, DIMD), cp128(st + 10240, B + i * BK, DIMD),
          compute_km, STG_KM, 10240, DIMD / BK);
    epi_h(g_Mth + ((size_t)b * CIN + mt * 128) * DIMD + nt * 128, DIMD, acc,
          nullptr, 0, g_vrs + b * DIMD + nt * 128);
}

// ---------------- K5: out = exp(v) @ Mth^T * (1/4096) + br ----------------
__global__ __launch_bounds__(256, 2)
void k_out(const float* __restrict__ br, float* __restrict__ out) {
    extern __shared__ __align__(16) char smem[];
    int nt = blockIdx.x, mt = blockIdx.y;     // nt fast dim -> A-tile L2 reuse
    int b = mt >> 5;
    const __half* A = g_vh + (size_t)mt * 128 * DIMD;               // exp(v)
    const __half* B = g_Mth + ((size_t)b * CIN + nt * 128) * DIMD;  // [c][v]
    uint32_t s0 = smem_u32(smem);
    float acc[4][4][4];
    zacc(acc);
    GEMM3(cp128(st, A + i * BK, DIMD), cp128(st + 10240, B + i * BK, DIMD),
          compute_km, STG_KM, 10240, DIMD / BK);
    epi_f(out + (size_t)mt * 128 * CIN + nt * 128, CIN, acc, br + nt * 128,
          1.0f / 4096.0f);
}

// ---------------- launch ----------------
extern "C" void kernel_launch(void* const* d_in, const int* in_sizes, int n_in,
                              void* d_out, int out_size) {
    (void)in_sizes; (void)n_in; (void)out_size;
    const float* x  = (const float*)d_in[0];
    const float* Wq = (const float*)d_in[1];
    const float* bq = (const float*)d_in[2];
    const float* Wk = (const float*)d_in[3];
    const float* bk = (const float*)d_in[4];
    const float* Wv = (const float*)d_in[5];
    const float* bv = (const float*)d_in[6];
    const float* Wr = (const float*)d_in[7];
    const float* br = (const float*)d_in[8];
    float* out = (float*)d_out;

    static int smem_set = 0;
    if (!smem_set) {
        cudaFuncSetAttribute(k_proj, cudaFuncAttributeMaxDynamicSharedMemorySize, 3 * STG_KM);
        cudaFuncSetAttribute(k_gd,   cudaFuncAttributeMaxDynamicSharedMemorySize, 3 * STG_GD);
        cudaFuncSetAttribute(k_m,    cudaFuncAttributeMaxDynamicSharedMemorySize, 3 * STG_KM);
        cudaFuncSetAttribute(k_out,  cudaFuncAttributeMaxDynamicSharedMemorySize, 3 * STG_KM);
        smem_set = 1;
    }

    __half* wrt = nullptr;
    cudaGetSymbolAddress((void**)&wrt, g_Wrth);

    k_cvtx<<<2048, 256>>>(x);                                     // #1
    k_trw3<<<dim3(8, 16, 3), dim3(32, 8)>>>(Wq, Wk, Wv);          // #2
    k_trh<<<dim3(16, 8), dim3(32, 8)>>>(Wr, wrt, DIMD, CIN);      // #3
    k_proj<<<dim3(6, NTOT / 128), 256, 3 * STG_KM>>>(bq, bk, bv); // #4 (ncu slot)
    k_colsum<<<dim3(NB * 8, 2), 256>>>();
    k_colfin<<<32, 256>>>();
    k_gd<<<NB * NSPLIT * 2 * 2, 256, 3 * STG_GD>>>();
    k_gdreduce<<<(NB * DIMD * DIMD) / 512, 256>>>();
    k_m<<<dim3(4, 2, NB), 256, 3 * STG_KM>>>();
    k_out<<<dim3(4, NTOT / 128), 256, 3 * STG_KM>>>(br, out);
}